// round 14
// baseline (speedup 1.0000x reference)
#include <cuda_runtime.h>
#include <cstdint>

#define B 4
#define L 256
#define H 256
#define HS 64
#define NEG_INF (-4294967295.0f)

// Scratch: pre-projected Q (scaled by 1/8), K'' = K + K_time, V'' = V + V_time
__device__ float g_Q[B * L * H];
__device__ float g_K[B * L * H];
__device__ float g_V[B * L * H];

// ---------------------------------------------------------------------------
// Kernel 1: three 1024x256x256 fp32 GEMMs (torch Linear: x @ W.T + b) with
// fused epilogues. z = 0: Q*0.125, z = 1: K + K_time, z = 2: V + V_time.
// BM=64, BN=32, BK=16, 128 threads, 4x4 microtile, float4 LDS both operands,
// register-prefetch pipeline. 8 x 16 x 3 = 384 CTAs.
// ---------------------------------------------------------------------------
__global__ __launch_bounds__(128) void proj_kernel(
    const float* __restrict__ queries, const float* __restrict__ keys,
    const float* __restrict__ Wq, const float* __restrict__ bq,
    const float* __restrict__ Wk, const float* __restrict__ bk,
    const float* __restrict__ Wv, const float* __restrict__ bv,
    const float* __restrict__ K_time, const float* __restrict__ V_time)
{
    const int z = blockIdx.z;
    const float* X    = (z == 0) ? queries : keys;
    const float* W    = (z == 0) ? Wq : (z == 1 ? Wk : Wv);
    const float* bias = (z == 0) ? bq : (z == 1 ? bk : bv);
    const float* add  = (z == 1) ? K_time : (z == 2 ? V_time : nullptr);
    float* out        = (z == 0) ? g_Q : (z == 1 ? g_K : g_V);

    const int rowBase = blockIdx.y * 64;   // gridDim.y = 16
    const int colBase = blockIdx.x * 32;   // gridDim.x = 8

    // k-major tiles, padded: row stride 68/36 floats (16B-aligned, low conflict)
    __shared__ __align__(16) float Xs[16][68];
    __shared__ __align__(16) float Ws[16][36];

    const int t  = threadIdx.x;
    const int tx = t & 7;        // 8 col groups * 4 cols
    const int ty = t >> 3;       // 16 row groups * 4 rows

    float acc[4][4];
#pragma unroll
    for (int i = 0; i < 4; i++)
#pragma unroll
        for (int j = 0; j < 4; j++) acc[i][j] = 0.0f;

    // prefetch tile 0 into registers
    float xreg[8], wreg[4];
#pragma unroll
    for (int i = 0; i < 8; i++) {
        int e = t + i * 128;
        xreg[i] = X[(size_t)(rowBase + (e >> 4)) * 256 + (e & 15)];
    }
#pragma unroll
    for (int i = 0; i < 4; i++) {
        int e = t + i * 128;
        wreg[i] = W[(size_t)(colBase + (e >> 4)) * 256 + (e & 15)];
    }

    for (int k0 = 0; k0 < 256; k0 += 16) {
#pragma unroll
        for (int i = 0; i < 8; i++) {
            int e = t + i * 128;
            Xs[e & 15][e >> 4] = xreg[i];
        }
#pragma unroll
        for (int i = 0; i < 4; i++) {
            int e = t + i * 128;
            Ws[e & 15][e >> 4] = wreg[i];
        }
        __syncthreads();

        if (k0 + 16 < 256) {        // prefetch next tile (overlaps compute)
            int kn = k0 + 16;
#pragma unroll
            for (int i = 0; i < 8; i++) {
                int e = t + i * 128;
                xreg[i] = X[(size_t)(rowBase + (e >> 4)) * 256 + kn + (e & 15)];
            }
#pragma unroll
            for (int i = 0; i < 4; i++) {
                int e = t + i * 128;
                wreg[i] = W[(size_t)(colBase + (e >> 4)) * 256 + kn + (e & 15)];
            }
        }

#pragma unroll
        for (int kk = 0; kk < 16; kk++) {
            float4 xa = *(const float4*)&Xs[kk][ty * 4];
            float4 wb = *(const float4*)&Ws[kk][tx * 4];
            acc[0][0] += xa.x * wb.x; acc[0][1] += xa.x * wb.y;
            acc[0][2] += xa.x * wb.z; acc[0][3] += xa.x * wb.w;
            acc[1][0] += xa.y * wb.x; acc[1][1] += xa.y * wb.y;
            acc[1][2] += xa.y * wb.z; acc[1][3] += xa.y * wb.w;
            acc[2][0] += xa.z * wb.x; acc[2][1] += xa.z * wb.y;
            acc[2][2] += xa.z * wb.z; acc[2][3] += xa.z * wb.w;
            acc[3][0] += xa.w * wb.x; acc[3][1] += xa.w * wb.y;
            acc[3][2] += xa.w * wb.z; acc[3][3] += xa.w * wb.w;
        }
        __syncthreads();
    }

    const int col = colBase + tx * 4;
    const float4 b4 = *(const float4*)&bias[col];
#pragma unroll
    for (int i = 0; i < 4; i++) {
        const int row = rowBase + ty * 4 + i;
        float4 v;
        v.x = acc[i][0] + b4.x; v.y = acc[i][1] + b4.y;
        v.z = acc[i][2] + b4.z; v.w = acc[i][3] + b4.w;
        if (z == 0) {
            v.x *= 0.125f; v.y *= 0.125f; v.z *= 0.125f; v.w *= 0.125f;
        } else {
            float4 a4 = *(const float4*)&add[(size_t)row * 256 + col];
            v.x += a4.x; v.y += a4.y; v.z += a4.z; v.w += a4.w;
        }
        *(float4*)&out[(size_t)row * 256 + col] = v;
    }
}

// ---------------------------------------------------------------------------
// Kernel 2: fused time-aware attention. One CTA per (b, q), 256 threads.
// ---------------------------------------------------------------------------
__global__ __launch_bounds__(256) void attn_kernel(
    const float* __restrict__ tK, const float* __restrict__ tV,
    const int* __restrict__ mask, float* __restrict__ out)
{
    const int b = blockIdx.y;
    const int q = blockIdx.x;
    const int t = threadIdx.x;
    const int ksub = t >> 6;
    const int cg   = t & 63;
    const int lane = t & 31;
    const int n    = cg >> 4;

    __shared__ __align__(16) float sQ[256];
    __shared__ __align__(16) float sS[4][256];
    __shared__ __align__(16) float4 pbuf[4][64];
    __shared__ float red[8];

    const size_t rowQ = (size_t)b * L + q;

    sQ[t] = g_Q[rowQ * 256 + t];
    __syncthreads();
    const float4 q4 = *(const float4*)&sQ[cg * 4];

    // -------- phase 1: scores --------
    const float4* tK4 = (const float4*)tK + rowQ * (L * 64);
    const float4* K4  = (const float4*)g_K + (size_t)b * L * 64;
#pragma unroll 4
    for (int k0 = 0; k0 < L; k0 += 4) {
        int k = k0 + ksub;
        float4 a  = __ldcs(&tK4[(size_t)k * 64 + cg]);   // streamed, read-once
        float4 kk = K4[(size_t)k * 64 + cg];
        int mk = mask[q * L + k];            // mask is int32 (bool widened)
        float p = q4.x * (a.x + kk.x) + q4.y * (a.y + kk.y)
                + q4.z * (a.z + kk.z) + q4.w * (a.w + kk.w);
        p += __shfl_xor_sync(0xffffffffu, p, 8);
        p += __shfl_xor_sync(0xffffffffu, p, 4);
        p += __shfl_xor_sync(0xffffffffu, p, 2);
        p += __shfl_xor_sync(0xffffffffu, p, 1);
        if ((cg & 15) == 0) {
            sS[n][k] = mk ? NEG_INF : p;
        }
    }
    __syncthreads();

    // -------- phase 2: softmax per head (warp w handles head w>>1, half w&1)
    {
        const int w  = t >> 5;
        const int hn = w >> 1;
        const int kb = (w & 1) * 128 + lane * 4;
        float4 v = *(const float4*)&sS[hn][kb];
        float m = fmaxf(fmaxf(v.x, v.y), fmaxf(v.z, v.w));
#pragma unroll
        for (int o = 16; o; o >>= 1) m = fmaxf(m, __shfl_xor_sync(0xffffffffu, m, o));
        if (lane == 0) red[w] = m;
        __syncthreads();
        const float hm = fmaxf(red[hn * 2], red[hn * 2 + 1]);
        v.x = __expf(v.x - hm); v.y = __expf(v.y - hm);
        v.z = __expf(v.z - hm); v.w = __expf(v.w - hm);
        float s = v.x + v.y + v.z + v.w;
#pragma unroll
        for (int o = 16; o; o >>= 1) s += __shfl_xor_sync(0xffffffffu, s, o);
        __syncthreads();               // all reads of red (max) done
        if (lane == 0) red[w] = s;
        __syncthreads();
        const float inv = 1.0f / (red[hn * 2] + red[hn * 2 + 1]);
        v.x *= inv; v.y *= inv; v.z *= inv; v.w *= inv;
        *(float4*)&sS[hn][kb] = v;
        __syncthreads();
    }

    // -------- phase 3: output --------
    const float4* tV4 = (const float4*)tV + rowQ * (L * 64);
    const float4* V4  = (const float4*)g_V + (size_t)b * L * 64;
    float4 acc = make_float4(0.f, 0.f, 0.f, 0.f);
#pragma unroll 4
    for (int k0 = 0; k0 < L; k0 += 4) {
        int k = k0 + ksub;
        float a = sS[n][k];
        float4 tv = __ldcs(&tV4[(size_t)k * 64 + cg]);   // streamed, read-once
        float4 vv = V4[(size_t)k * 64 + cg];
        acc.x += a * (tv.x + vv.x);
        acc.y += a * (tv.y + vv.y);
        acc.z += a * (tv.z + vv.z);
        acc.w += a * (tv.w + vv.w);
    }
    pbuf[ksub][cg] = acc;
    __syncthreads();

    // reduce over the 4 ksub partials; pbuf flat float layout: [ksub][c]
    const float* pb = (const float*)pbuf;
    float sum = pb[0 * 256 + t] + pb[1 * 256 + t] + pb[2 * 256 + t] + pb[3 * 256 + t];
    out[rowQ * 256 + t] = sum;
}

extern "C" void kernel_launch(void* const* d_in, const int* in_sizes, int n_in,
                              void* d_out, int out_size)
{
    const float* queries = (const float*)d_in[0];
    const float* keys    = (const float*)d_in[1];
    const int*   mask    = (const int*)d_in[2];
    const float* tK      = (const float*)d_in[3];
    const float* tV      = (const float*)d_in[4];
    const float* K_time  = (const float*)d_in[5];
    const float* V_time  = (const float*)d_in[6];
    const float* Wq = (const float*)d_in[7];
    const float* bq = (const float*)d_in[8];
    const float* Wk = (const float*)d_in[9];
    const float* bk = (const float*)d_in[10];
    const float* Wv = (const float*)d_in[11];
    const float* bv = (const float*)d_in[12];

    proj_kernel<<<dim3(8, 16, 3), 128>>>(queries, keys, Wq, bq, Wk, bk, Wv, bv,
                                         K_time, V_time);
    attn_kernel<<<dim3(L, B), 256>>>(tK, tV, mask, (float*)d_out);
}

// round 17
// speedup vs baseline: 1.2105x; 1.2105x over previous
#include <cuda_runtime.h>
#include <cstdint>

#define B 4
#define L 256
#define H 256
#define HS 64
#define NEG_INF (-4294967295.0f)

// Scratch: pre-projected Q (scaled by 1/8), K'' = K + K_time, V'' = V + V_time
__device__ float g_Q[B * L * H];
__device__ float g_K[B * L * H];
__device__ float g_V[B * L * H];

// ---------------------------------------------------------------------------
// Kernel 1: three 1024x256x256 fp32 GEMMs (torch Linear: x @ W.T + b) with
// fused epilogues. z = 0: Q*0.125, z = 1: K + K_time, z = 2: V + V_time.
// BM=64, BN=32, BK=16, 128 threads, 4x4 microtile, float4 LDS both operands,
// register-prefetch pipeline. (R14-measured: cut proj+gap from ~41us to ~15us)
// ---------------------------------------------------------------------------
__global__ __launch_bounds__(128) void proj_kernel(
    const float* __restrict__ queries, const float* __restrict__ keys,
    const float* __restrict__ Wq, const float* __restrict__ bq,
    const float* __restrict__ Wk, const float* __restrict__ bk,
    const float* __restrict__ Wv, const float* __restrict__ bv,
    const float* __restrict__ K_time, const float* __restrict__ V_time)
{
    const int z = blockIdx.z;
    const float* X    = (z == 0) ? queries : keys;
    const float* W    = (z == 0) ? Wq : (z == 1 ? Wk : Wv);
    const float* bias = (z == 0) ? bq : (z == 1 ? bk : bv);
    const float* add  = (z == 1) ? K_time : (z == 2 ? V_time : nullptr);
    float* out        = (z == 0) ? g_Q : (z == 1 ? g_K : g_V);

    const int rowBase = blockIdx.y * 64;   // gridDim.y = 16
    const int colBase = blockIdx.x * 32;   // gridDim.x = 8

    __shared__ __align__(16) float Xs[16][68];
    __shared__ __align__(16) float Ws[16][36];

    const int t  = threadIdx.x;
    const int tx = t & 7;        // 8 col groups * 4 cols
    const int ty = t >> 3;       // 16 row groups * 4 rows

    float acc[4][4];
#pragma unroll
    for (int i = 0; i < 4; i++)
#pragma unroll
        for (int j = 0; j < 4; j++) acc[i][j] = 0.0f;

    // prefetch tile 0 into registers
    float xreg[8], wreg[4];
#pragma unroll
    for (int i = 0; i < 8; i++) {
        int e = t + i * 128;
        xreg[i] = X[(size_t)(rowBase + (e >> 4)) * 256 + (e & 15)];
    }
#pragma unroll
    for (int i = 0; i < 4; i++) {
        int e = t + i * 128;
        wreg[i] = W[(size_t)(colBase + (e >> 4)) * 256 + (e & 15)];
    }

    for (int k0 = 0; k0 < 256; k0 += 16) {
#pragma unroll
        for (int i = 0; i < 8; i++) {
            int e = t + i * 128;
            Xs[e & 15][e >> 4] = xreg[i];
        }
#pragma unroll
        for (int i = 0; i < 4; i++) {
            int e = t + i * 128;
            Ws[e & 15][e >> 4] = wreg[i];
        }
        __syncthreads();

        if (k0 + 16 < 256) {        // prefetch next tile (overlaps compute)
            int kn = k0 + 16;
#pragma unroll
            for (int i = 0; i < 8; i++) {
                int e = t + i * 128;
                xreg[i] = X[(size_t)(rowBase + (e >> 4)) * 256 + kn + (e & 15)];
            }
#pragma unroll
            for (int i = 0; i < 4; i++) {
                int e = t + i * 128;
                wreg[i] = W[(size_t)(colBase + (e >> 4)) * 256 + kn + (e & 15)];
            }
        }

#pragma unroll
        for (int kk = 0; kk < 16; kk++) {
            float4 xa = *(const float4*)&Xs[kk][ty * 4];
            float4 wb = *(const float4*)&Ws[kk][tx * 4];
            acc[0][0] += xa.x * wb.x; acc[0][1] += xa.x * wb.y;
            acc[0][2] += xa.x * wb.z; acc[0][3] += xa.x * wb.w;
            acc[1][0] += xa.y * wb.x; acc[1][1] += xa.y * wb.y;
            acc[1][2] += xa.y * wb.z; acc[1][3] += xa.y * wb.w;
            acc[2][0] += xa.z * wb.x; acc[2][1] += xa.z * wb.y;
            acc[2][2] += xa.z * wb.z; acc[2][3] += xa.z * wb.w;
            acc[3][0] += xa.w * wb.x; acc[3][1] += xa.w * wb.y;
            acc[3][2] += xa.w * wb.z; acc[3][3] += xa.w * wb.w;
        }
        __syncthreads();
    }

    const int col = colBase + tx * 4;
    const float4 b4 = *(const float4*)&bias[col];
#pragma unroll
    for (int i = 0; i < 4; i++) {
        const int row = rowBase + ty * 4 + i;
        float4 v;
        v.x = acc[i][0] + b4.x; v.y = acc[i][1] + b4.y;
        v.z = acc[i][2] + b4.z; v.w = acc[i][3] + b4.w;
        if (z == 0) {
            v.x *= 0.125f; v.y *= 0.125f; v.z *= 0.125f; v.w *= 0.125f;
        } else {
            float4 a4 = *(const float4*)&add[(size_t)row * 256 + col];
            v.x += a4.x; v.y += a4.y; v.z += a4.z; v.w += a4.w;
        }
        *(float4*)&out[(size_t)row * 256 + col] = v;
    }
}

// ---------------------------------------------------------------------------
// Kernel 2: fused time-aware attention. One CTA per (b, q), 256 threads.
// R3-measured config: 32 regs, 8 CTA/SM, 77.7% DRAM. __ldcs reverted (R14
// showed it cost 12 regs -> occ 49% -> DRAM 60%). min-blocks=8 pins regs<=32.
// ---------------------------------------------------------------------------
__global__ __launch_bounds__(256, 8) void attn_kernel(
    const float* __restrict__ tK, const float* __restrict__ tV,
    const int* __restrict__ mask, float* __restrict__ out)
{
    const int b = blockIdx.y;
    const int q = blockIdx.x;
    const int t = threadIdx.x;
    const int ksub = t >> 6;
    const int cg   = t & 63;
    const int lane = t & 31;
    const int n    = cg >> 4;

    __shared__ __align__(16) float sQ[256];
    __shared__ __align__(16) float sS[4][256];
    __shared__ __align__(16) float4 pbuf[4][64];
    __shared__ float red[8];

    const size_t rowQ = (size_t)b * L + q;

    sQ[t] = g_Q[rowQ * 256 + t];
    __syncthreads();
    const float4 q4 = *(const float4*)&sQ[cg * 4];

    // -------- phase 1: scores --------
    const float4* tK4 = (const float4*)tK + rowQ * (L * 64);
    const float4* K4  = (const float4*)g_K + (size_t)b * L * 64;
#pragma unroll 4
    for (int k0 = 0; k0 < L; k0 += 4) {
        int k = k0 + ksub;
        float4 a  = tK4[(size_t)k * 64 + cg];
        float4 kk = K4[(size_t)k * 64 + cg];
        int mk = mask[q * L + k];            // mask is int32 (bool widened)
        float p = q4.x * (a.x + kk.x) + q4.y * (a.y + kk.y)
                + q4.z * (a.z + kk.z) + q4.w * (a.w + kk.w);
        p += __shfl_xor_sync(0xffffffffu, p, 8);
        p += __shfl_xor_sync(0xffffffffu, p, 4);
        p += __shfl_xor_sync(0xffffffffu, p, 2);
        p += __shfl_xor_sync(0xffffffffu, p, 1);
        if ((cg & 15) == 0) {
            sS[n][k] = mk ? NEG_INF : p;
        }
    }
    __syncthreads();

    // -------- phase 2: softmax per head (warp w handles head w>>1, half w&1)
    {
        const int w  = t >> 5;
        const int hn = w >> 1;
        const int kb = (w & 1) * 128 + lane * 4;
        float4 v = *(const float4*)&sS[hn][kb];
        float m = fmaxf(fmaxf(v.x, v.y), fmaxf(v.z, v.w));
#pragma unroll
        for (int o = 16; o; o >>= 1) m = fmaxf(m, __shfl_xor_sync(0xffffffffu, m, o));
        if (lane == 0) red[w] = m;
        __syncthreads();
        const float hm = fmaxf(red[hn * 2], red[hn * 2 + 1]);
        v.x = __expf(v.x - hm); v.y = __expf(v.y - hm);
        v.z = __expf(v.z - hm); v.w = __expf(v.w - hm);
        float s = v.x + v.y + v.z + v.w;
#pragma unroll
        for (int o = 16; o; o >>= 1) s += __shfl_xor_sync(0xffffffffu, s, o);
        __syncthreads();               // all reads of red (max) done
        if (lane == 0) red[w] = s;
        __syncthreads();
        const float inv = 1.0f / (red[hn * 2] + red[hn * 2 + 1]);
        v.x *= inv; v.y *= inv; v.z *= inv; v.w *= inv;
        *(float4*)&sS[hn][kb] = v;
        __syncthreads();
    }

    // -------- phase 3: output --------
    const float4* tV4 = (const float4*)tV + rowQ * (L * 64);
    const float4* V4  = (const float4*)g_V + (size_t)b * L * 64;
    float4 acc = make_float4(0.f, 0.f, 0.f, 0.f);
#pragma unroll 4
    for (int k0 = 0; k0 < L; k0 += 4) {
        int k = k0 + ksub;
        float a = sS[n][k];
        float4 tv = tV4[(size_t)k * 64 + cg];
        float4 vv = V4[(size_t)k * 64 + cg];
        acc.x += a * (tv.x + vv.x);
        acc.y += a * (tv.y + vv.y);
        acc.z += a * (tv.z + vv.z);
        acc.w += a * (tv.w + vv.w);
    }
    pbuf[ksub][cg] = acc;
    __syncthreads();

    // reduce over the 4 ksub partials; pbuf flat float layout: [ksub][c]
    const float* pb = (const float*)pbuf;
    float sum = pb[0 * 256 + t] + pb[1 * 256 + t] + pb[2 * 256 + t] + pb[3 * 256 + t];
    out[rowQ * 256 + t] = sum;
}

extern "C" void kernel_launch(void* const* d_in, const int* in_sizes, int n_in,
                              void* d_out, int out_size)
{
    const float* queries = (const float*)d_in[0];
    const float* keys    = (const float*)d_in[1];
    const int*   mask    = (const int*)d_in[2];
    const float* tK      = (const float*)d_in[3];
    const float* tV      = (const float*)d_in[4];
    const float* K_time  = (const float*)d_in[5];
    const float* V_time  = (const float*)d_in[6];
    const float* Wq = (const float*)d_in[7];
    const float* bq = (const float*)d_in[8];
    const float* Wk = (const float*)d_in[9];
    const float* bk = (const float*)d_in[10];
    const float* Wv = (const float*)d_in[11];
    const float* bv = (const float*)d_in[12];

    proj_kernel<<<dim3(8, 16, 3), 128>>>(queries, keys, Wq, bq, Wk, bk, Wv, bv,
                                         K_time, V_time);
    attn_kernel<<<dim3(L, B), 256>>>(tK, tV, mask, (float*)d_out);
}